// round 2
// baseline (speedup 1.0000x reference)
#include <cuda_runtime.h>
#include <math.h>

// R1 resubmission (R0 bench hit GPUAcquisitionTimeout — no data).
// Chunked-overlap parallel IIR:
//   y1[t] = bh0*x[t] + bh1*x[t-1] - ah1*y1[t-1]   (1st-order highpass)
//   y2[t] = bl0*y1[t] + bl1*y1[t-1] - al1*y2[t-1] (1st-order lowpass)
// Stable poles (~0.906, ~0.848) => initial-state error decays as pole^W.
// Each thread owns one L-sample chunk of one row, warms state on the
// preceding W samples (residual ~1.5e-7 at W=160), then emits L outputs.

#define CHUNK_L 512
#define WARM_W  160
#define BATCH_B 128

__device__ float g_coef[8]; // bh0, bh1, -ah1, bl0, bl1, -al1, gain

__global__ void bp_coef_kernel(const float* __restrict__ cf,
                               const float* __restrict__ bw,
                               const float* __restrict__ gain,
                               const int*   __restrict__ sr) {
    double nyq = 0.5 * (double)(*sr);
    double c = (double)(*cf);
    double b = (double)(*bw);
    double lw = (c - 0.5 * b) / nyq;
    double hw = (c + 0.5 * b) / nyq;
    double K1 = tan(M_PI * lw * 0.5);
    double K2 = tan(M_PI * hw * 0.5);
    double bh0 = 1.0 / (K1 + 1.0);
    double ah1 = (K1 - 1.0) / (K1 + 1.0);
    double bl0 = K2 / (K2 + 1.0);
    double al1 = (K2 - 1.0) / (K2 + 1.0);
    g_coef[0] = (float)bh0;
    g_coef[1] = (float)(-bh0);
    g_coef[2] = (float)(-ah1);
    g_coef[3] = (float)bl0;
    g_coef[4] = (float)bl0;
    g_coef[5] = (float)(-al1);
    g_coef[6] = *gain;
}

#define BP_STEP(XT, YO)                                  \
    do {                                                 \
        float _y1 = fmaf(bh1, xp, bh0 * (XT));           \
        _y1 = fmaf(nah1, y1p, _y1);                      \
        float _y2 = fmaf(bl1, y1p, bl0 * _y1);           \
        _y2 = fmaf(nal1, y2p, _y2);                      \
        xp = (XT); y1p = _y1; y2p = _y2;                 \
        (YO) = _y2 * gain;                               \
    } while (0)

#define BP_STEP_NOOUT(XT)                                \
    do {                                                 \
        float _y1 = fmaf(bh1, xp, bh0 * (XT));           \
        _y1 = fmaf(nah1, y1p, _y1);                      \
        float _y2 = fmaf(bl1, y1p, bl0 * _y1);           \
        _y2 = fmaf(nal1, y2p, _y2);                      \
        xp = (XT); y1p = _y1; y2p = _y2;                 \
    } while (0)

__global__ __launch_bounds__(128)
void bp_filter_kernel(const float* __restrict__ x,
                      float* __restrict__ out,
                      int T, int chunks_per_row) {
    int idx = blockIdx.x * blockDim.x + threadIdx.x;
    int b = idx / chunks_per_row;
    int c = idx - b * chunks_per_row;
    if (b >= BATCH_B) return;

    const float bh0  = g_coef[0];
    const float bh1  = g_coef[1];
    const float nah1 = g_coef[2];
    const float bl0  = g_coef[3];
    const float bl1  = g_coef[4];
    const float nal1 = g_coef[5];
    const float gain = g_coef[6];

    const float* __restrict__ xrow = x + (size_t)b * (size_t)T;
    float* __restrict__ yrow = out + (size_t)b * (size_t)T;
    const int start = c * CHUNK_L;

    float xp = 0.f, y1p = 0.f, y2p = 0.f;

    // ---- warmup (skipped for chunk 0: exact zero initial state) ----
    if (c > 0) {
        const float4* __restrict__ wv =
            (const float4*)(xrow + start - WARM_W);
        #pragma unroll 4
        for (int i = 0; i < WARM_W / 4; ++i) {
            float4 v = wv[i];
            BP_STEP_NOOUT(v.x);
            BP_STEP_NOOUT(v.y);
            BP_STEP_NOOUT(v.z);
            BP_STEP_NOOUT(v.w);
        }
    }

    // ---- main chunk: read float4, emit float4 ----
    const float4* __restrict__ xv = (const float4*)(xrow + start);
    float4* __restrict__ yv = (float4*)(yrow + start);
    #pragma unroll 4
    for (int i = 0; i < CHUNK_L / 4; ++i) {
        float4 v = xv[i];
        float4 o;
        BP_STEP(v.x, o.x);
        BP_STEP(v.y, o.y);
        BP_STEP(v.z, o.z);
        BP_STEP(v.w, o.w);
        yv[i] = o;
    }
}

extern "C" void kernel_launch(void* const* d_in, const int* in_sizes, int n_in,
                              void* d_out, int out_size) {
    const float* x    = (const float*)d_in[0];
    const float* cf   = (const float*)d_in[1];
    const float* bw   = (const float*)d_in[2];
    const float* gain = (const float*)d_in[3];
    const int*   sr   = (const int*)d_in[4];
    float* out = (float*)d_out;

    int total = in_sizes[0];
    int T = total / BATCH_B;
    int chunks = T / CHUNK_L;

    bp_coef_kernel<<<1, 1>>>(cf, bw, gain, sr);

    int nthreads = BATCH_B * chunks;
    int block = 128;
    int grid = (nthreads + block - 1) / block;
    bp_filter_kernel<<<grid, block>>>(x, out, T, chunks);
}

// round 4
// speedup vs baseline: 1.4375x; 1.4375x over previous
#include <cuda_runtime.h>
#include <math.h>

// R4 = R3 resubmission (R3 bench hit GPUAcquisitionTimeout — no data).
// L=256, W=128 (4096 warps: occ ~43%), unroll 8 for front-batched LDGs.
// Chunked-overlap parallel IIR; poles ~0.906/0.848 => warmup W=128
// leaves state error ~3.4e-6 << 1e-3 budget. Chunk 0 exact.

#define CHUNK_L 256
#define WARM_W  128
#define BATCH_B 128

__device__ float g_coef[8]; // bh0, bh1, -ah1, bl0, bl1, -al1, gain

__global__ void bp_coef_kernel(const float* __restrict__ cf,
                               const float* __restrict__ bw,
                               const float* __restrict__ gain,
                               const int*   __restrict__ sr) {
    double nyq = 0.5 * (double)(*sr);
    double c = (double)(*cf);
    double b = (double)(*bw);
    double lw = (c - 0.5 * b) / nyq;
    double hw = (c + 0.5 * b) / nyq;
    double K1 = tan(M_PI * lw * 0.5);
    double K2 = tan(M_PI * hw * 0.5);
    double bh0 = 1.0 / (K1 + 1.0);
    double ah1 = (K1 - 1.0) / (K1 + 1.0);
    double bl0 = K2 / (K2 + 1.0);
    double al1 = (K2 - 1.0) / (K2 + 1.0);
    g_coef[0] = (float)bh0;
    g_coef[1] = (float)(-bh0);
    g_coef[2] = (float)(-ah1);
    g_coef[3] = (float)bl0;
    g_coef[4] = (float)bl0;
    g_coef[5] = (float)(-al1);
    g_coef[6] = *gain;
}

#define BP_STEP(XT, YO)                                  \
    do {                                                 \
        float _y1 = fmaf(bh1, xp, bh0 * (XT));           \
        _y1 = fmaf(nah1, y1p, _y1);                      \
        float _y2 = fmaf(bl1, y1p, bl0 * _y1);           \
        _y2 = fmaf(nal1, y2p, _y2);                      \
        xp = (XT); y1p = _y1; y2p = _y2;                 \
        (YO) = _y2 * gain;                               \
    } while (0)

#define BP_STEP_NOOUT(XT)                                \
    do {                                                 \
        float _y1 = fmaf(bh1, xp, bh0 * (XT));           \
        _y1 = fmaf(nah1, y1p, _y1);                      \
        float _y2 = fmaf(bl1, y1p, bl0 * _y1);           \
        _y2 = fmaf(nal1, y2p, _y2);                      \
        xp = (XT); y1p = _y1; y2p = _y2;                 \
    } while (0)

__global__ __launch_bounds__(128)
void bp_filter_kernel(const float* __restrict__ x,
                      float* __restrict__ out,
                      int T, int chunks_per_row) {
    int idx = blockIdx.x * blockDim.x + threadIdx.x;
    int b = idx / chunks_per_row;
    int c = idx - b * chunks_per_row;
    if (b >= BATCH_B) return;

    const float bh0  = g_coef[0];
    const float bh1  = g_coef[1];
    const float nah1 = g_coef[2];
    const float bl0  = g_coef[3];
    const float bl1  = g_coef[4];
    const float nal1 = g_coef[5];
    const float gain = g_coef[6];

    const float* __restrict__ xrow = x + (size_t)b * (size_t)T;
    float* __restrict__ yrow = out + (size_t)b * (size_t)T;
    const int start = c * CHUNK_L;

    float xp = 0.f, y1p = 0.f, y2p = 0.f;

    // ---- warmup (skipped for chunk 0: exact zero initial state) ----
    if (c > 0) {
        const float4* __restrict__ wv =
            (const float4*)(xrow + start - WARM_W);
        #pragma unroll 8
        for (int i = 0; i < WARM_W / 4; ++i) {
            float4 v = wv[i];
            BP_STEP_NOOUT(v.x);
            BP_STEP_NOOUT(v.y);
            BP_STEP_NOOUT(v.z);
            BP_STEP_NOOUT(v.w);
        }
    }

    // ---- main chunk: read float4, emit float4 ----
    const float4* __restrict__ xv = (const float4*)(xrow + start);
    float4* __restrict__ yv = (float4*)(yrow + start);
    #pragma unroll 8
    for (int i = 0; i < CHUNK_L / 4; ++i) {
        float4 v = xv[i];
        float4 o;
        BP_STEP(v.x, o.x);
        BP_STEP(v.y, o.y);
        BP_STEP(v.z, o.z);
        BP_STEP(v.w, o.w);
        yv[i] = o;
    }
}

extern "C" void kernel_launch(void* const* d_in, const int* in_sizes, int n_in,
                              void* d_out, int out_size) {
    const float* x    = (const float*)d_in[0];
    const float* cf   = (const float*)d_in[1];
    const float* bw   = (const float*)d_in[2];
    const float* gain = (const float*)d_in[3];
    const int*   sr   = (const int*)d_in[4];
    float* out = (float*)d_out;

    int total = in_sizes[0];
    int T = total / BATCH_B;
    int chunks = T / CHUNK_L;

    bp_coef_kernel<<<1, 1>>>(cf, bw, gain, sr);

    int nthreads = BATCH_B * chunks;
    int block = 128;
    int grid = (nthreads + block - 1) / block;
    bp_filter_kernel<<<grid, block>>>(x, out, T, chunks);
}